// round 7
// baseline (speedup 1.0000x reference)
#include <cuda_runtime.h>
#include <cuda_bf16.h>
#include <cstdint>

#define NMAX 50000
#define NPAD 50176
#define EMAX 800000
#define FD   128

// ---------------- scratch (device globals) ---------------------------------
__device__ int   g_cnti[NMAX];
__device__ int   g_off [NMAX + 1];
__device__ int   g_cur [NMAX];
__device__ int   g_part[256];
__device__ int   g_csr [EMAX];
__device__ float g_x1f [NMAX * FD];                 // fp32 x1 (for gather2)
// bf16 hi/lo planes for GEMM A operands (row-major [NPAD x 128] each)
__device__ __nv_bfloat16 g_xh [(size_t)NPAD * FD];
__device__ __nv_bfloat16 g_xl [(size_t)NPAD * FD];
__device__ __nv_bfloat16 g_x1h[(size_t)NPAD * FD];
__device__ __nv_bfloat16 g_x1l[(size_t)NPAD * FD];
__device__ __nv_bfloat16 g_a1h[(size_t)NPAD * FD];
__device__ __nv_bfloat16 g_a1l[(size_t)NPAD * FD];
__device__ __nv_bfloat16 g_a2h[(size_t)NPAD * FD];
__device__ __nv_bfloat16 g_a2l[(size_t)NPAD * FD];
// weights: 3 layers x [128 out x 256 k] (k = [Wl | Wr]), bf16 hi/lo
__device__ __nv_bfloat16 g_wh[3 * 128 * 256];
__device__ __nv_bfloat16 g_wl[3 * 128 * 256];

// ---------------- split helpers ---------------------------------------------
__device__ __forceinline__ void split2(float a, float b, uint32_t& hi, uint32_t& lo) {
    __nv_bfloat16 ah = __float2bfloat16(a);
    __nv_bfloat16 bh = __float2bfloat16(b);
    __nv_bfloat162 h2 = __nv_bfloat162(ah, bh);
    __nv_bfloat162 l2 = __nv_bfloat162(__float2bfloat16(a - __bfloat162float(ah)),
                                       __float2bfloat16(b - __bfloat162float(bh)));
    hi = *(uint32_t*)&h2;
    lo = *(uint32_t*)&l2;
}

__device__ __forceinline__ void split_store(float v, __nv_bfloat16* h, __nv_bfloat16* l) {
    __nv_bfloat16 hb = __float2bfloat16(v);
    *h = hb;
    *l = __float2bfloat16(v - __bfloat162float(hb));
}

// ---------------- CSR build -------------------------------------------------
__global__ void zero_cnt(int n) {
    int i = blockIdx.x * blockDim.x + threadIdx.x;
    if (i < n) g_cnti[i] = 0;
}

__global__ void hist_kernel(const int* __restrict__ dst, int E, int n) {
    int e = blockIdx.x * blockDim.x + threadIdx.x;
    if (e < E) {
        int d = dst[e];
        if ((unsigned)d < (unsigned)n) atomicAdd(&g_cnti[d], 1);
    }
}

__global__ void part_kernel(int n) {
    __shared__ int buf[256];
    int i = blockIdx.x * 256 + threadIdx.x;
    buf[threadIdx.x] = (i < n) ? g_cnti[i] : 0;
    __syncthreads();
    for (int s = 128; s > 0; s >>= 1) {
        if (threadIdx.x < s) buf[threadIdx.x] += buf[threadIdx.x + s];
        __syncthreads();
    }
    if (threadIdx.x == 0) g_part[blockIdx.x] = buf[0];
}

__global__ void scan_part(int nb) {           // parallel exclusive scan, nb<=256
    __shared__ int buf[256];
    int tid = threadIdx.x;
    int v = (tid < nb) ? g_part[tid] : 0;
    buf[tid] = v;
    __syncthreads();
    for (int s = 1; s < 256; s <<= 1) {
        int t = (tid >= s) ? buf[tid - s] : 0;
        __syncthreads();
        buf[tid] += t;
        __syncthreads();
    }
    if (tid < nb) g_part[tid] = buf[tid] - v;
}

__global__ void offsets_kernel(int n) {
    __shared__ int buf[256];
    int tid = threadIdx.x;
    int i = blockIdx.x * 256 + tid;
    int c = (i < n) ? g_cnti[i] : 0;
    buf[tid] = c;
    __syncthreads();
    for (int s = 1; s < 256; s <<= 1) {
        int t = (tid >= s) ? buf[tid - s] : 0;
        __syncthreads();
        buf[tid] += t;
        __syncthreads();
    }
    int off = g_part[blockIdx.x] + buf[tid] - c;
    if (i < n) { g_off[i] = off; g_cur[i] = off; }
    if (i == n - 1) g_off[n] = off + c;
}

__global__ void fill_kernel(const int* __restrict__ src,
                            const int* __restrict__ dst, int E, int n) {
    int e = blockIdx.x * blockDim.x + threadIdx.x;
    if (e < E) {
        int d = dst[e], s = src[e];
        if ((unsigned)d < (unsigned)n && (unsigned)s < (unsigned)n) {
            int pos = atomicAdd(&g_cur[d], 1);
            g_csr[pos] = s;
        }
    }
}

// ---------------- gather: mean-agg, writes bf16 hi/lo planes ----------------
__global__ void gather_kernel(const float* __restrict__ feat,
                              __nv_bfloat16* __restrict__ aggH,
                              __nv_bfloat16* __restrict__ aggL, int n) {
    int gt = blockIdx.x * blockDim.x + threadIdx.x;
    int node = gt >> 5, lane = gt & 31;
    if (node >= n) return;
    int beg = __ldg(&g_off[node]);
    int end = __ldg(&g_off[node + 1]);
    float4 acc = make_float4(0.f, 0.f, 0.f, 0.f);
    int j = beg;
    for (; j + 8 <= end; j += 8) {
        int si[8];
#pragma unroll
        for (int i = 0; i < 8; i++) si[i] = __ldg(&g_csr[j + i]);
        float4 v[8];
#pragma unroll
        for (int i = 0; i < 8; i++)
            v[i] = __ldg(((const float4*)(feat + (size_t)si[i] * FD)) + lane);
#pragma unroll
        for (int i = 0; i < 8; i++) {
            acc.x += v[i].x; acc.y += v[i].y; acc.z += v[i].z; acc.w += v[i].w;
        }
    }
    for (; j + 4 <= end; j += 4) {
        int si[4];
#pragma unroll
        for (int i = 0; i < 4; i++) si[i] = __ldg(&g_csr[j + i]);
        float4 v[4];
#pragma unroll
        for (int i = 0; i < 4; i++)
            v[i] = __ldg(((const float4*)(feat + (size_t)si[i] * FD)) + lane);
#pragma unroll
        for (int i = 0; i < 4; i++) {
            acc.x += v[i].x; acc.y += v[i].y; acc.z += v[i].z; acc.w += v[i].w;
        }
    }
    for (; j < end; j++) {
        int s = __ldg(&g_csr[j]);
        float4 v = __ldg(((const float4*)(feat + (size_t)s * FD)) + lane);
        acc.x += v.x; acc.y += v.y; acc.z += v.z; acc.w += v.w;
    }
    int deg = end - beg;
    float sc = (deg > 0) ? (1.0f / (float)deg) : 0.0f;
    acc.x *= sc; acc.y *= sc; acc.z *= sc; acc.w *= sc;
    uint32_t h0, l0, h1, l1;
    split2(acc.x, acc.y, h0, l0);
    split2(acc.z, acc.w, h1, l1);
    size_t o = (size_t)node * FD + (size_t)lane * 4;
    *(uint2*)&aggH[o] = make_uint2(h0, h1);
    *(uint2*)&aggL[o] = make_uint2(l0, l1);
}

// ---------------- converts ---------------------------------------------------
__global__ void conv_x(const float* __restrict__ src, int n) {
    int q = blockIdx.x * blockDim.x + threadIdx.x;
    if (q >= n * 32) return;
    int row = q >> 5, c4 = (q & 31) << 2;
    float4 v = __ldg((const float4*)(src + (size_t)row * FD + c4));
    uint32_t h0, l0, h1, l1;
    split2(v.x, v.y, h0, l0);
    split2(v.z, v.w, h1, l1);
    size_t o = (size_t)row * FD + c4;
    *(uint2*)&g_xh[o] = make_uint2(h0, h1);
    *(uint2*)&g_xl[o] = make_uint2(l0, l1);
}

__global__ void conv_w(const float* W1l, const float* W1r,
                       const float* W2l, const float* W2r,
                       const float* W3l, const float* W3r) {
    int q = blockIdx.x * blockDim.x + threadIdx.x;
    if (q >= 3 * 128 * 64) return;
    int L = q / 8192, rem = q % 8192;
    int o = rem >> 6, kq = (rem & 63) << 2;
    const float* Wl = (L == 0) ? W1l : (L == 1) ? W2l : W3l;
    const float* Wr = (L == 0) ? W1r : (L == 1) ? W2r : W3r;
    const float* sp = (kq < 128) ? (Wl + o * 128 + kq) : (Wr + o * 128 + kq - 128);
    float4 v = __ldg((const float4*)sp);
    size_t out = (size_t)L * 32768 + (size_t)o * 256 + kq;
    split_store(v.x, g_wh + out + 0, g_wl + out + 0);
    split_store(v.y, g_wh + out + 1, g_wl + out + 1);
    split_store(v.z, g_wh + out + 2, g_wl + out + 2);
    split_store(v.w, g_wh + out + 3, g_wl + out + 3);
}

// ---------------- mma.sync bf16 GEMM ----------------------------------------
#define PS   136
#define BUFB (128 * PS * 2)

__device__ __forceinline__ uint32_t smem_u32(const void* p) {
    uint32_t a;
    asm("{ .reg .u64 t; cvta.to.shared.u64 t, %1; cvt.u32.u64 %0, t; }" : "=r"(a) : "l"(p));
    return a;
}

__device__ __forceinline__ void ldm_x4(uint32_t* r, uint32_t addr) {
    asm volatile("ldmatrix.sync.aligned.m8n8.x4.shared.b16 {%0,%1,%2,%3}, [%4];"
                 : "=r"(r[0]), "=r"(r[1]), "=r"(r[2]), "=r"(r[3]) : "r"(addr));
}

__device__ __forceinline__ void mma_bf16(float* d, const uint32_t* a, const uint32_t* b) {
    asm volatile("mma.sync.aligned.m16n8k16.row.col.f32.bf16.bf16.f32 "
                 "{%0,%1,%2,%3}, {%4,%5,%6,%7}, {%8,%9}, {%0,%1,%2,%3};"
                 : "+f"(d[0]), "+f"(d[1]), "+f"(d[2]), "+f"(d[3])
                 : "r"(a[0]), "r"(a[1]), "r"(a[2]), "r"(a[3]), "r"(b[0]), "r"(b[1]));
}

// ---- layer-1 GEMM: 256 threads, relu, writes x1 fp32 + hi/lo planes --------
#define G1_AH 0
#define G1_AL (BUFB)
#define G1_WH (2 * BUFB)
#define G1_WL (3 * BUFB)
#define G1_SMEM (4 * BUFB)

__global__ void __launch_bounds__(256, 1)
gemm1(const __nv_bfloat16* __restrict__ AggH, const __nv_bfloat16* __restrict__ AggL,
      const __nv_bfloat16* __restrict__ SelfH, const __nv_bfloat16* __restrict__ SelfL,
      const __nv_bfloat16* __restrict__ Whi, const __nv_bfloat16* __restrict__ Wlo,
      const float* __restrict__ bias, float* __restrict__ outF,
      __nv_bfloat16* __restrict__ outH, __nv_bfloat16* __restrict__ outL, int n) {
    extern __shared__ __align__(16) char smem[];
    uint32_t sb = smem_u32(smem);
    int tid = threadIdx.x, wid = tid >> 5, lane = tid & 31;
    int base_row = blockIdx.x * 128;

    int m_warp = (wid & 3) * 32;
    int n_warp = (wid >> 2) * 64;

    float acc[2][8][4];
#pragma unroll
    for (int i = 0; i < 2; i++)
#pragma unroll
        for (int j = 0; j < 8; j++)
#pragma unroll
            for (int k = 0; k < 4; k++) acc[i][j][k] = 0.0f;

    int g = lane >> 3, lr = lane & 7;
    int a_row = (g & 1) * 8 + lr;
    int a_col = (g >> 1) * 8;

    for (int kc = 0; kc < 2; kc++) {
        if (kc) __syncthreads();
        const __nv_bfloat16* Sh = kc ? SelfH : AggH;
        const __nv_bfloat16* Sl = kc ? SelfL : AggL;
#pragma unroll
        for (int i = 0; i < 8; i++) {
            int q = tid + i * 256;            // 0..2047, 16 uint4 per row
            int row = q >> 4;
            int c8 = (q & 15) * 8;
            size_t gi = (size_t)(base_row + row) * FD + c8;
            uint32_t so = (uint32_t)(row * PS + c8) * 2;
            *(uint4*)(smem + G1_AH + so) = *(const uint4*)(Sh + gi);
            *(uint4*)(smem + G1_AL + so) = *(const uint4*)(Sl + gi);
            size_t gW = (size_t)row * 256 + kc * 128 + c8;
            *(uint4*)(smem + G1_WH + so) = *(const uint4*)(Whi + gW);
            *(uint4*)(smem + G1_WL + so) = *(const uint4*)(Wlo + gW);
        }
        __syncthreads();

#pragma unroll
        for (int k16 = 0; k16 < 8; k16++) {
            int kb = k16 * 16;
            uint32_t ah[2][4], al[2][4];
#pragma unroll
            for (int mi = 0; mi < 2; mi++) {
                uint32_t ad = sb + (uint32_t)((m_warp + mi * 16 + a_row) * PS + kb + a_col) * 2;
                ldm_x4(ah[mi], G1_AH + ad);
                ldm_x4(al[mi], G1_AL + ad);
            }
            uint32_t bh[8][2], bl[8][2];
#pragma unroll
            for (int np = 0; np < 4; np++) {
                uint32_t bd = sb + (uint32_t)((n_warp + np * 16 + a_row) * PS + kb + a_col) * 2;
                uint32_t t[4];
                ldm_x4(t, G1_WH + bd);
                bh[np * 2 + 0][0] = t[0]; bh[np * 2 + 0][1] = t[2];
                bh[np * 2 + 1][0] = t[1]; bh[np * 2 + 1][1] = t[3];
                ldm_x4(t, G1_WL + bd);
                bl[np * 2 + 0][0] = t[0]; bl[np * 2 + 0][1] = t[2];
                bl[np * 2 + 1][0] = t[1]; bl[np * 2 + 1][1] = t[3];
            }
#pragma unroll
            for (int mi = 0; mi < 2; mi++)
#pragma unroll
                for (int ni = 0; ni < 8; ni++) {
                    mma_bf16(acc[mi][ni], ah[mi], bh[ni]);
                    mma_bf16(acc[mi][ni], ah[mi], bl[ni]);
                    mma_bf16(acc[mi][ni], al[mi], bh[ni]);
                }
        }
    }

    int r_in = lane >> 2;
    int c_in = (lane & 3) * 2;
#pragma unroll
    for (int mi = 0; mi < 2; mi++)
#pragma unroll
        for (int half = 0; half < 2; half++) {
            int gr = base_row + m_warp + mi * 16 + r_in + half * 8;
            if (gr >= n) continue;
#pragma unroll
            for (int ni = 0; ni < 8; ni++) {
                int col = n_warp + ni * 8 + c_in;
                float y0 = fmaxf(acc[mi][ni][half * 2 + 0] + __ldg(bias + col + 0), 0.f);
                float y1 = fmaxf(acc[mi][ni][half * 2 + 1] + __ldg(bias + col + 1), 0.f);
                *(float2*)(outF + (size_t)gr * FD + col) = make_float2(y0, y1);
                uint32_t h, l;
                split2(y0, y1, h, l);
                *(uint32_t*)&outH[(size_t)gr * FD + col] = h;
                *(uint32_t*)&outL[(size_t)gr * FD + col] = l;
            }
        }
}

// ---- fused layers 2+3: 512 threads; warps 0-7 -> out1 (W2), 8-15 -> out2 ---
#define G2_AH 0
#define G2_AL (BUFB)
#define G2_W2H (2 * BUFB)
#define G2_W2L (3 * BUFB)
#define G2_W3H (4 * BUFB)
#define G2_W3L (5 * BUFB)
#define G2_SMEM (6 * BUFB)

__global__ void __launch_bounds__(512, 1)
gemm23(const __nv_bfloat16* __restrict__ AggH, const __nv_bfloat16* __restrict__ AggL,
       const __nv_bfloat16* __restrict__ SelfH, const __nv_bfloat16* __restrict__ SelfL,
       const __nv_bfloat16* __restrict__ W2hi, const __nv_bfloat16* __restrict__ W2lo,
       const __nv_bfloat16* __restrict__ W3hi, const __nv_bfloat16* __restrict__ W3lo,
       const float* __restrict__ b2, const float* __restrict__ b3,
       float* __restrict__ out1, float* __restrict__ out2, int n) {
    extern __shared__ __align__(16) char smem[];
    uint32_t sb = smem_u32(smem);
    int tid = threadIdx.x, wid = tid >> 5, lane = tid & 31;
    int base_row = blockIdx.x * 128;

    int layer = wid >> 3;
    int m_warp = (wid & 3) * 32;
    int n_warp = ((wid >> 2) & 1) * 64;
    uint32_t offWH = layer ? G2_W3H : G2_W2H;
    uint32_t offWL = layer ? G2_W3L : G2_W2L;

    float acc[2][8][4];
#pragma unroll
    for (int i = 0; i < 2; i++)
#pragma unroll
        for (int j = 0; j < 8; j++)
#pragma unroll
            for (int k = 0; k < 4; k++) acc[i][j][k] = 0.0f;

    int g = lane >> 3, lr = lane & 7;
    int a_row = (g & 1) * 8 + lr;
    int a_col = (g >> 1) * 8;

    for (int kc = 0; kc < 2; kc++) {
        if (kc) __syncthreads();
        const __nv_bfloat16* Sh = kc ? SelfH : AggH;
        const __nv_bfloat16* Sl = kc ? SelfL : AggL;
#pragma unroll
        for (int i = 0; i < 4; i++) {
            int q = tid + i * 512;            // 0..2047
            int row = q >> 4;
            int c8 = (q & 15) * 8;
            size_t gi = (size_t)(base_row + row) * FD + c8;
            uint32_t so = (uint32_t)(row * PS + c8) * 2;
            *(uint4*)(smem + G2_AH + so) = *(const uint4*)(Sh + gi);
            *(uint4*)(smem + G2_AL + so) = *(const uint4*)(Sl + gi);
            size_t gW = (size_t)row * 256 + kc * 128 + c8;
            *(uint4*)(smem + G2_W2H + so) = *(const uint4*)(W2hi + gW);
            *(uint4*)(smem + G2_W2L + so) = *(const uint4*)(W2lo + gW);
            *(uint4*)(smem + G2_W3H + so) = *(const uint4*)(W3hi + gW);
            *(uint4*)(smem + G2_W3L + so) = *(const uint4*)(W3lo + gW);
        }
        __syncthreads();

#pragma unroll
        for (int k16 = 0; k16 < 8; k16++) {
            int kb = k16 * 16;
            uint32_t ah[2][4], al[2][4];
#pragma unroll
            for (int mi = 0; mi < 2; mi++) {
                uint32_t ad = sb + (uint32_t)((m_warp + mi * 16 + a_row) * PS + kb + a_col) * 2;
                ldm_x4(ah[mi], G2_AH + ad);
                ldm_x4(al[mi], G2_AL + ad);
            }
            uint32_t bh[8][2], bl[8][2];
#pragma unroll
            for (int np = 0; np < 4; np++) {
                uint32_t bd = sb + (uint32_t)((n_warp + np * 16 + a_row) * PS + kb + a_col) * 2;
                uint32_t t[4];
                ldm_x4(t, offWH + bd);
                bh[np * 2 + 0][0] = t[0]; bh[np * 2 + 0][1] = t[2];
                bh[np * 2 + 1][0] = t[1]; bh[np * 2 + 1][1] = t[3];
                ldm_x4(t, offWL + bd);
                bl[np * 2 + 0][0] = t[0]; bl[np * 2 + 0][1] = t[2];
                bl[np * 2 + 1][0] = t[1]; bl[np * 2 + 1][1] = t[3];
            }
#pragma unroll
            for (int mi = 0; mi < 2; mi++)
#pragma unroll
                for (int ni = 0; ni < 8; ni++) {
                    mma_bf16(acc[mi][ni], ah[mi], bh[ni]);
                    mma_bf16(acc[mi][ni], ah[mi], bl[ni]);
                    mma_bf16(acc[mi][ni], al[mi], bh[ni]);
                }
        }
    }

    const float* bias = layer ? b3 : b2;
    float* outF = layer ? out2 : out1;
    int r_in = lane >> 2;
    int c_in = (lane & 3) * 2;
#pragma unroll
    for (int mi = 0; mi < 2; mi++)
#pragma unroll
        for (int half = 0; half < 2; half++) {
            int gr = base_row + m_warp + mi * 16 + r_in + half * 8;
            if (gr >= n) continue;
#pragma unroll
            for (int ni = 0; ni < 8; ni++) {
                int col = n_warp + ni * 8 + c_in;
                float y0 = acc[mi][ni][half * 2 + 0] + __ldg(bias + col + 0);
                float y1 = acc[mi][ni][half * 2 + 1] + __ldg(bias + col + 1);
                *(float2*)(outF + (size_t)gr * FD + col) = make_float2(y0, y1);
            }
        }
}

// ---------------- launch ----------------------------------------------------
extern "C" void kernel_launch(void* const* d_in, const int* in_sizes, int n_in,
                              void* d_out, int out_size) {
    const float* x   = (const float*)d_in[0];
    const int*   ei  = (const int*)d_in[1];
    const float* W1l = (const float*)d_in[2];
    const float* b1l = (const float*)d_in[3];
    const float* W1r = (const float*)d_in[4];
    const float* W2l = (const float*)d_in[5];
    const float* b2l = (const float*)d_in[6];
    const float* W2r = (const float*)d_in[7];
    const float* W3l = (const float*)d_in[8];
    const float* b3l = (const float*)d_in[9];
    const float* W3r = (const float*)d_in[10];

    int n = in_sizes[0] / FD;
    int E = in_sizes[1] / 2;
    const int* src = ei;
    const int* dst = ei + E;

    float* out_h1 = (float*)d_out;
    float* out_h2 = (float*)d_out + (size_t)n * FD;

    void *px1f = 0, *pxh = 0, *pxl = 0, *px1h = 0, *px1l = 0;
    void *pa1h = 0, *pa1l = 0, *pa2h = 0, *pa2l = 0, *pwh = 0, *pwl = 0;
    cudaGetSymbolAddress(&px1f, g_x1f);
    cudaGetSymbolAddress(&pxh,  g_xh);
    cudaGetSymbolAddress(&pxl,  g_xl);
    cudaGetSymbolAddress(&px1h, g_x1h);
    cudaGetSymbolAddress(&px1l, g_x1l);
    cudaGetSymbolAddress(&pa1h, g_a1h);
    cudaGetSymbolAddress(&pa1l, g_a1l);
    cudaGetSymbolAddress(&pa2h, g_a2h);
    cudaGetSymbolAddress(&pa2l, g_a2l);
    cudaGetSymbolAddress(&pwh,  g_wh);
    cudaGetSymbolAddress(&pwl,  g_wl);
    float* x1f = (float*)px1f;
    __nv_bfloat16 *xh = (__nv_bfloat16*)pxh,  *xl = (__nv_bfloat16*)pxl;
    __nv_bfloat16 *x1h = (__nv_bfloat16*)px1h, *x1l = (__nv_bfloat16*)px1l;
    __nv_bfloat16 *a1h = (__nv_bfloat16*)pa1h, *a1l = (__nv_bfloat16*)pa1l;
    __nv_bfloat16 *a2h = (__nv_bfloat16*)pa2h, *a2l = (__nv_bfloat16*)pa2l;
    __nv_bfloat16 *wh = (__nv_bfloat16*)pwh,   *wl = (__nv_bfloat16*)pwl;

    cudaFuncSetAttribute(gemm1,  cudaFuncAttributeMaxDynamicSharedMemorySize, G1_SMEM);
    cudaFuncSetAttribute(gemm23, cudaFuncAttributeMaxDynamicSharedMemorySize, G2_SMEM);

    int nblocks256 = (n + 255) / 256;
    int eblocks = (E + 255) / 256;
    int gabl = (n * 32 + 255) / 256;
    int cblocks = (n * 32 + 255) / 256;
    int gblocks = (n + 127) / 128;

    // CSR build
    zero_cnt<<<nblocks256, 256>>>(n);
    hist_kernel<<<eblocks, 256>>>(dst, E, n);
    part_kernel<<<nblocks256, 256>>>(n);
    scan_part<<<1, 256>>>(nblocks256);
    offsets_kernel<<<nblocks256, 256>>>(n);
    fill_kernel<<<eblocks, 256>>>(src, dst, E, n);
    conv_w<<<(3 * 128 * 64 + 255) / 256, 256>>>(W1l, W1r, W2l, W2r, W3l, W3r);
    conv_x<<<cblocks, 256>>>(x, n);

    // layer 1
    gather_kernel<<<gabl, 256>>>(x, a1h, a1l, n);
    gemm1<<<gblocks, 256, G1_SMEM>>>(a1h, a1l, xh, xl, wh, wl, b1l,
                                     x1f, x1h, x1l, n);

    // layers 2 + 3
    gather_kernel<<<gabl, 256>>>(x1f, a2h, a2l, n);
    gemm23<<<gblocks, 512, G2_SMEM>>>(a2h, a2l, x1h, x1l,
                                      wh + 32768, wl + 32768,
                                      wh + 65536, wl + 65536,
                                      b2l, b3l, out_h1, out_h2, n);
}

// round 8
// speedup vs baseline: 1.1392x; 1.1392x over previous
#include <cuda_runtime.h>
#include <cuda_bf16.h>
#include <cstdint>

#define NMAX 50000
#define EMAX 800000
#define FD   128

// ---------------- scratch (device globals) ---------------------------------
__device__ float g_agg1[NMAX * FD];
__device__ float g_x1  [NMAX * FD];
__device__ float g_agg2[NMAX * FD];
__device__ int   g_cnti[NMAX];
__device__ int   g_off [NMAX + 1];
__device__ int   g_cur [NMAX];
__device__ int   g_part[256];
__device__ int   g_csr [EMAX];
// weights: 3 layers x [128 out x 256 k]  (k = [Wl | Wr]), bf16 hi/lo split
__device__ __nv_bfloat16 g_wh[3 * 128 * 256];
__device__ __nv_bfloat16 g_wl[3 * 128 * 256];

// ---------------- CSR build -------------------------------------------------
__global__ void zero_cnt(int n) {
    int i = blockIdx.x * blockDim.x + threadIdx.x;
    if (i < n) g_cnti[i] = 0;
}

__global__ void hist_kernel(const int* __restrict__ dst, int E, int n) {
    int e = blockIdx.x * blockDim.x + threadIdx.x;
    if (e < E) {
        int d = dst[e];
        if ((unsigned)d < (unsigned)n) atomicAdd(&g_cnti[d], 1);
    }
}

__global__ void part_kernel(int n) {          // block sums of 256-chunks
    __shared__ int buf[256];
    int i = blockIdx.x * 256 + threadIdx.x;
    buf[threadIdx.x] = (i < n) ? g_cnti[i] : 0;
    __syncthreads();
    for (int s = 128; s > 0; s >>= 1) {
        if (threadIdx.x < s) buf[threadIdx.x] += buf[threadIdx.x + s];
        __syncthreads();
    }
    if (threadIdx.x == 0) g_part[blockIdx.x] = buf[0];
}

__global__ void scan_part(int nb) {           // parallel exclusive scan, nb<=256
    __shared__ int buf[256];
    int tid = threadIdx.x;
    int v = (tid < nb) ? g_part[tid] : 0;
    buf[tid] = v;
    __syncthreads();
    for (int s = 1; s < 256; s <<= 1) {
        int t = (tid >= s) ? buf[tid - s] : 0;
        __syncthreads();
        buf[tid] += t;
        __syncthreads();
    }
    if (tid < nb) g_part[tid] = buf[tid] - v;
}

__global__ void offsets_kernel(int n) {       // in-block exclusive scan + base
    __shared__ int buf[256];
    int tid = threadIdx.x;
    int i = blockIdx.x * 256 + tid;
    int c = (i < n) ? g_cnti[i] : 0;
    buf[tid] = c;
    __syncthreads();
    for (int s = 1; s < 256; s <<= 1) {
        int t = (tid >= s) ? buf[tid - s] : 0;
        __syncthreads();
        buf[tid] += t;
        __syncthreads();
    }
    int off = g_part[blockIdx.x] + buf[tid] - c;   // exclusive
    if (i < n) { g_off[i] = off; g_cur[i] = off; }
    if (i == n - 1) g_off[n] = off + c;
}

__global__ void fill_kernel(const int* __restrict__ src,
                            const int* __restrict__ dst, int E, int n) {
    int e = blockIdx.x * blockDim.x + threadIdx.x;
    if (e < E) {
        int d = dst[e], s = src[e];
        if ((unsigned)d < (unsigned)n && (unsigned)s < (unsigned)n) {
            int pos = atomicAdd(&g_cur[d], 1);
            g_csr[pos] = s;
        }
    }
}

// ---------------- gather aggregation (mean folded in) ------------------------
__global__ void gather_kernel(const float* __restrict__ feat,
                              float* __restrict__ agg, int n) {
    int gt = blockIdx.x * blockDim.x + threadIdx.x;
    int node = gt >> 5, lane = gt & 31;
    if (node >= n) return;
    int beg = __ldg(&g_off[node]);
    int end = __ldg(&g_off[node + 1]);
    float4 acc = make_float4(0.f, 0.f, 0.f, 0.f);
    int j = beg;
    for (; j + 4 <= end; j += 4) {
        int s0 = __ldg(&g_csr[j + 0]);
        int s1 = __ldg(&g_csr[j + 1]);
        int s2 = __ldg(&g_csr[j + 2]);
        int s3 = __ldg(&g_csr[j + 3]);
        float4 v0 = __ldg(((const float4*)(feat + (size_t)s0 * FD)) + lane);
        float4 v1 = __ldg(((const float4*)(feat + (size_t)s1 * FD)) + lane);
        float4 v2 = __ldg(((const float4*)(feat + (size_t)s2 * FD)) + lane);
        float4 v3 = __ldg(((const float4*)(feat + (size_t)s3 * FD)) + lane);
        acc.x += v0.x + v1.x + v2.x + v3.x;
        acc.y += v0.y + v1.y + v2.y + v3.y;
        acc.z += v0.z + v1.z + v2.z + v3.z;
        acc.w += v0.w + v1.w + v2.w + v3.w;
    }
    for (; j < end; j++) {
        int s = __ldg(&g_csr[j]);
        float4 v = __ldg(((const float4*)(feat + (size_t)s * FD)) + lane);
        acc.x += v.x; acc.y += v.y; acc.z += v.z; acc.w += v.w;
    }
    int deg = end - beg;
    float sc = (deg > 0) ? (1.0f / (float)deg) : 0.0f;
    acc.x *= sc; acc.y *= sc; acc.z *= sc; acc.w *= sc;
    *(((float4*)(agg + (size_t)node * FD)) + lane) = acc;
}

// ---------------- weight split ----------------------------------------------
__device__ __forceinline__ void split2(float a, float b, uint32_t& hi, uint32_t& lo) {
    __nv_bfloat16 ah = __float2bfloat16(a);
    __nv_bfloat16 bh = __float2bfloat16(b);
    __nv_bfloat162 h2 = __nv_bfloat162(ah, bh);
    __nv_bfloat162 l2 = __nv_bfloat162(__float2bfloat16(a - __bfloat162float(ah)),
                                       __float2bfloat16(b - __bfloat162float(bh)));
    hi = *(uint32_t*)&h2;
    lo = *(uint32_t*)&l2;
}

__device__ __forceinline__ void split_store(float v, __nv_bfloat16* h, __nv_bfloat16* l) {
    __nv_bfloat16 hb = __float2bfloat16(v);
    *h = hb;
    *l = __float2bfloat16(v - __bfloat162float(hb));
}

__global__ void conv_w(const float* W1l, const float* W1r,
                       const float* W2l, const float* W2r,
                       const float* W3l, const float* W3r) {
    int q = blockIdx.x * blockDim.x + threadIdx.x;
    if (q >= 3 * 128 * 64) return;
    int L = q / 8192, rem = q % 8192;
    int o = rem >> 6, kq = (rem & 63) << 2;
    const float* Wl = (L == 0) ? W1l : (L == 1) ? W2l : W3l;
    const float* Wr = (L == 0) ? W1r : (L == 1) ? W2r : W3r;
    const float* sp = (kq < 128) ? (Wl + o * 128 + kq) : (Wr + o * 128 + kq - 128);
    float4 v = __ldg((const float4*)sp);
    size_t out = (size_t)L * 32768 + (size_t)o * 256 + kq;
    split_store(v.x, g_wh + out + 0, g_wl + out + 0);
    split_store(v.y, g_wh + out + 1, g_wl + out + 1);
    split_store(v.z, g_wh + out + 2, g_wl + out + 2);
    split_store(v.w, g_wh + out + 3, g_wl + out + 3);
}

// ---------------- mma.sync bf16 GEMM ----------------------------------------
#define PS   136
#define BUFB (128 * PS * 2)

__device__ __forceinline__ uint32_t smem_u32(const void* p) {
    uint32_t a;
    asm("{ .reg .u64 t; cvta.to.shared.u64 t, %1; cvt.u32.u64 %0, t; }" : "=r"(a) : "l"(p));
    return a;
}

__device__ __forceinline__ void ldm_x4(uint32_t* r, uint32_t addr) {
    asm volatile("ldmatrix.sync.aligned.m8n8.x4.shared.b16 {%0,%1,%2,%3}, [%4];"
                 : "=r"(r[0]), "=r"(r[1]), "=r"(r[2]), "=r"(r[3]) : "r"(addr));
}

__device__ __forceinline__ void mma_bf16(float* d, const uint32_t* a, const uint32_t* b) {
    asm volatile("mma.sync.aligned.m16n8k16.row.col.f32.bf16.bf16.f32 "
                 "{%0,%1,%2,%3}, {%4,%5,%6,%7}, {%8,%9}, {%0,%1,%2,%3};"
                 : "+f"(d[0]), "+f"(d[1]), "+f"(d[2]), "+f"(d[3])
                 : "r"(a[0]), "r"(a[1]), "r"(a[2]), "r"(a[3]), "r"(b[0]), "r"(b[1]));
}

// ---- layer-1 GEMM: 256 threads, one output, relu ----
#define G1_AH 0
#define G1_AL (BUFB)
#define G1_WH (2 * BUFB)
#define G1_WL (3 * BUFB)
#define G1_SMEM (4 * BUFB)

__global__ void __launch_bounds__(256, 1)
gemm1(const float* __restrict__ Aagg, const float* __restrict__ Aself,
      const __nv_bfloat16* __restrict__ Whi, const __nv_bfloat16* __restrict__ Wlo,
      const float* __restrict__ bias, float* __restrict__ outF, int n) {
    extern __shared__ __align__(16) char smem[];
    uint32_t sb = smem_u32(smem);
    int tid = threadIdx.x, wid = tid >> 5, lane = tid & 31;
    int base_row = blockIdx.x * 128;

    int m_warp = (wid & 3) * 32;
    int n_warp = (wid >> 2) * 64;

    float acc[2][8][4];
#pragma unroll
    for (int i = 0; i < 2; i++)
#pragma unroll
        for (int j = 0; j < 8; j++)
#pragma unroll
            for (int k = 0; k < 4; k++) acc[i][j][k] = 0.0f;

    int g = lane >> 3, lr = lane & 7;
    int a_row = (g & 1) * 8 + lr;
    int a_col = (g >> 1) * 8;

    for (int kc = 0; kc < 2; kc++) {
        if (kc) __syncthreads();
        const float* S = kc ? Aself : Aagg;
#pragma unroll
        for (int i = 0; i < 16; i++) {
            int q = tid + i * 256;
            int row = q >> 5;
            int c4 = (q & 31) << 2;
            int gr = base_row + row;
            float4 v = (gr < n) ? __ldg((const float4*)(S + (size_t)gr * FD + c4))
                                : make_float4(0.f, 0.f, 0.f, 0.f);
            uint32_t h0, l0, h1, l1;
            split2(v.x, v.y, h0, l0);
            split2(v.z, v.w, h1, l1);
            uint32_t so = (uint32_t)(row * PS + c4) * 2;
            *(uint2*)(smem + G1_AH + so) = make_uint2(h0, h1);
            *(uint2*)(smem + G1_AL + so) = make_uint2(l0, l1);
        }
#pragma unroll
        for (int i = 0; i < 8; i++) {
            int q = tid + i * 256;
            int row = q >> 4;
            int c8 = (q & 15) * 8;
            size_t gW = (size_t)row * 256 + kc * 128 + c8;
            uint32_t so = (uint32_t)(row * PS + c8) * 2;
            *(uint4*)(smem + G1_WH + so) = *(const uint4*)(Whi + gW);
            *(uint4*)(smem + G1_WL + so) = *(const uint4*)(Wlo + gW);
        }
        __syncthreads();

#pragma unroll
        for (int k16 = 0; k16 < 8; k16++) {
            int kb = k16 * 16;
            uint32_t ah[2][4], al[2][4];
#pragma unroll
            for (int mi = 0; mi < 2; mi++) {
                uint32_t ad = sb + (uint32_t)((m_warp + mi * 16 + a_row) * PS + kb + a_col) * 2;
                ldm_x4(ah[mi], G1_AH + ad);
                ldm_x4(al[mi], G1_AL + ad);
            }
            uint32_t bh[8][2], bl[8][2];
#pragma unroll
            for (int np = 0; np < 4; np++) {
                uint32_t bd = sb + (uint32_t)((n_warp + np * 16 + a_row) * PS + kb + a_col) * 2;
                uint32_t t[4];
                ldm_x4(t, G1_WH + bd);
                bh[np * 2 + 0][0] = t[0]; bh[np * 2 + 0][1] = t[2];
                bh[np * 2 + 1][0] = t[1]; bh[np * 2 + 1][1] = t[3];
                ldm_x4(t, G1_WL + bd);
                bl[np * 2 + 0][0] = t[0]; bl[np * 2 + 0][1] = t[2];
                bl[np * 2 + 1][0] = t[1]; bl[np * 2 + 1][1] = t[3];
            }
#pragma unroll
            for (int mi = 0; mi < 2; mi++)
#pragma unroll
                for (int ni = 0; ni < 8; ni++) {
                    mma_bf16(acc[mi][ni], ah[mi], bh[ni]);
                    mma_bf16(acc[mi][ni], ah[mi], bl[ni]);
                    mma_bf16(acc[mi][ni], al[mi], bh[ni]);
                }
        }
    }

    int r_in = lane >> 2;
    int c_in = (lane & 3) * 2;
#pragma unroll
    for (int mi = 0; mi < 2; mi++)
#pragma unroll
        for (int half = 0; half < 2; half++) {
            int gr = base_row + m_warp + mi * 16 + r_in + half * 8;
            if (gr >= n) continue;
#pragma unroll
            for (int ni = 0; ni < 8; ni++) {
                int col = n_warp + ni * 8 + c_in;
                float y0 = fmaxf(acc[mi][ni][half * 2 + 0] + __ldg(bias + col + 0), 0.f);
                float y1 = fmaxf(acc[mi][ni][half * 2 + 1] + __ldg(bias + col + 1), 0.f);
                *(float2*)(outF + (size_t)gr * FD + col) = make_float2(y0, y1);
            }
        }
}

// ---- fused layers 2+3: 512 threads; warps 0-7 -> out1 (W2), 8-15 -> out2 ---
#define G2_AH 0
#define G2_AL (BUFB)
#define G2_W2H (2 * BUFB)
#define G2_W2L (3 * BUFB)
#define G2_W3H (4 * BUFB)
#define G2_W3L (5 * BUFB)
#define G2_SMEM (6 * BUFB)

__global__ void __launch_bounds__(512, 1)
gemm23(const float* __restrict__ Aagg, const float* __restrict__ Aself,
       const __nv_bfloat16* __restrict__ W2hi, const __nv_bfloat16* __restrict__ W2lo,
       const __nv_bfloat16* __restrict__ W3hi, const __nv_bfloat16* __restrict__ W3lo,
       const float* __restrict__ b2, const float* __restrict__ b3,
       float* __restrict__ out1, float* __restrict__ out2, int n) {
    extern __shared__ __align__(16) char smem[];
    uint32_t sb = smem_u32(smem);
    int tid = threadIdx.x, wid = tid >> 5, lane = tid & 31;
    int base_row = blockIdx.x * 128;

    int layer = wid >> 3;                 // 0 or 1
    int m_warp = (wid & 3) * 32;
    int n_warp = ((wid >> 2) & 1) * 64;
    uint32_t offWH = layer ? G2_W3H : G2_W2H;
    uint32_t offWL = layer ? G2_W3L : G2_W2L;

    float acc[2][8][4];
#pragma unroll
    for (int i = 0; i < 2; i++)
#pragma unroll
        for (int j = 0; j < 8; j++)
#pragma unroll
            for (int k = 0; k < 4; k++) acc[i][j][k] = 0.0f;

    int g = lane >> 3, lr = lane & 7;
    int a_row = (g & 1) * 8 + lr;
    int a_col = (g >> 1) * 8;

    for (int kc = 0; kc < 2; kc++) {
        if (kc) __syncthreads();
        const float* S = kc ? Aself : Aagg;
        // A: 4096 float4 slots over 512 threads = 8 iters
#pragma unroll
        for (int i = 0; i < 8; i++) {
            int q = tid + i * 512;
            int row = q >> 5;
            int c4 = (q & 31) << 2;
            int gr = base_row + row;
            float4 v = (gr < n) ? __ldg((const float4*)(S + (size_t)gr * FD + c4))
                                : make_float4(0.f, 0.f, 0.f, 0.f);
            uint32_t h0, l0, h1, l1;
            split2(v.x, v.y, h0, l0);
            split2(v.z, v.w, h1, l1);
            uint32_t so = (uint32_t)(row * PS + c4) * 2;
            *(uint2*)(smem + G2_AH + so) = make_uint2(h0, h1);
            *(uint2*)(smem + G2_AL + so) = make_uint2(l0, l1);
        }
        // W2 + W3: each 2048 uint4 slots over 512 threads = 4 iters each
#pragma unroll
        for (int i = 0; i < 4; i++) {
            int q = tid + i * 512;
            int row = q >> 4;
            int c8 = (q & 15) * 8;
            size_t gW = (size_t)row * 256 + kc * 128 + c8;
            uint32_t so = (uint32_t)(row * PS + c8) * 2;
            *(uint4*)(smem + G2_W2H + so) = *(const uint4*)(W2hi + gW);
            *(uint4*)(smem + G2_W2L + so) = *(const uint4*)(W2lo + gW);
            *(uint4*)(smem + G2_W3H + so) = *(const uint4*)(W3hi + gW);
            *(uint4*)(smem + G2_W3L + so) = *(const uint4*)(W3lo + gW);
        }
        __syncthreads();

#pragma unroll
        for (int k16 = 0; k16 < 8; k16++) {
            int kb = k16 * 16;
            uint32_t ah[2][4], al[2][4];
#pragma unroll
            for (int mi = 0; mi < 2; mi++) {
                uint32_t ad = sb + (uint32_t)((m_warp + mi * 16 + a_row) * PS + kb + a_col) * 2;
                ldm_x4(ah[mi], G2_AH + ad);
                ldm_x4(al[mi], G2_AL + ad);
            }
            uint32_t bh[8][2], bl[8][2];
#pragma unroll
            for (int np = 0; np < 4; np++) {
                uint32_t bd = sb + (uint32_t)((n_warp + np * 16 + a_row) * PS + kb + a_col) * 2;
                uint32_t t[4];
                ldm_x4(t, offWH + bd);
                bh[np * 2 + 0][0] = t[0]; bh[np * 2 + 0][1] = t[2];
                bh[np * 2 + 1][0] = t[1]; bh[np * 2 + 1][1] = t[3];
                ldm_x4(t, offWL + bd);
                bl[np * 2 + 0][0] = t[0]; bl[np * 2 + 0][1] = t[2];
                bl[np * 2 + 1][0] = t[1]; bl[np * 2 + 1][1] = t[3];
            }
#pragma unroll
            for (int mi = 0; mi < 2; mi++)
#pragma unroll
                for (int ni = 0; ni < 8; ni++) {
                    mma_bf16(acc[mi][ni], ah[mi], bh[ni]);
                    mma_bf16(acc[mi][ni], ah[mi], bl[ni]);
                    mma_bf16(acc[mi][ni], al[mi], bh[ni]);
                }
        }
    }

    const float* bias = layer ? b3 : b2;
    float* outF = layer ? out2 : out1;
    int r_in = lane >> 2;
    int c_in = (lane & 3) * 2;
#pragma unroll
    for (int mi = 0; mi < 2; mi++)
#pragma unroll
        for (int half = 0; half < 2; half++) {
            int gr = base_row + m_warp + mi * 16 + r_in + half * 8;
            if (gr >= n) continue;
#pragma unroll
            for (int ni = 0; ni < 8; ni++) {
                int col = n_warp + ni * 8 + c_in;
                float y0 = acc[mi][ni][half * 2 + 0] + __ldg(bias + col + 0);
                float y1 = acc[mi][ni][half * 2 + 1] + __ldg(bias + col + 1);
                *(float2*)(outF + (size_t)gr * FD + col) = make_float2(y0, y1);
            }
        }
}

// ---------------- launch ----------------------------------------------------
extern "C" void kernel_launch(void* const* d_in, const int* in_sizes, int n_in,
                              void* d_out, int out_size) {
    const float* x   = (const float*)d_in[0];
    const int*   ei  = (const int*)d_in[1];
    const float* W1l = (const float*)d_in[2];
    const float* b1l = (const float*)d_in[3];
    const float* W1r = (const float*)d_in[4];
    const float* W2l = (const float*)d_in[5];
    const float* b2l = (const float*)d_in[6];
    const float* W2r = (const float*)d_in[7];
    const float* W3l = (const float*)d_in[8];
    const float* b3l = (const float*)d_in[9];
    const float* W3r = (const float*)d_in[10];

    int n = in_sizes[0] / FD;
    int E = in_sizes[1] / 2;
    const int* src = ei;
    const int* dst = ei + E;

    float* out_h1 = (float*)d_out;
    float* out_h2 = (float*)d_out + (size_t)n * FD;

    void *pa1 = 0, *pa2 = 0, *px1 = 0, *pwh = 0, *pwl = 0;
    cudaGetSymbolAddress(&pa1, g_agg1);
    cudaGetSymbolAddress(&pa2, g_agg2);
    cudaGetSymbolAddress(&px1, g_x1);
    cudaGetSymbolAddress(&pwh, g_wh);
    cudaGetSymbolAddress(&pwl, g_wl);
    float* agg1 = (float*)pa1;
    float* agg2 = (float*)pa2;
    float* x1   = (float*)px1;
    __nv_bfloat16* wh = (__nv_bfloat16*)pwh;
    __nv_bfloat16* wl = (__nv_bfloat16*)pwl;

    cudaFuncSetAttribute(gemm1,  cudaFuncAttributeMaxDynamicSharedMemorySize, G1_SMEM);
    cudaFuncSetAttribute(gemm23, cudaFuncAttributeMaxDynamicSharedMemorySize, G2_SMEM);

    int nblocks256 = (n + 255) / 256;
    int eblocks = (E + 255) / 256;
    int gabl = (n * 32 + 255) / 256;
    int gblocks = (n + 127) / 128;

    // CSR build
    zero_cnt<<<nblocks256, 256>>>(n);
    hist_kernel<<<eblocks, 256>>>(dst, E, n);
    part_kernel<<<nblocks256, 256>>>(n);
    scan_part<<<1, 256>>>(nblocks256);
    offsets_kernel<<<nblocks256, 256>>>(n);
    fill_kernel<<<eblocks, 256>>>(src, dst, E, n);
    conv_w<<<(3 * 128 * 64 + 255) / 256, 256>>>(W1l, W1r, W2l, W2r, W3l, W3r);

    // layer 1
    gather_kernel<<<gabl, 256>>>(x, agg1, n);
    gemm1<<<gblocks, 256, G1_SMEM>>>(agg1, x, wh, wl, b1l, x1, n);

    // layers 2 + 3 (shared aggregation, fused GEMM)
    gather_kernel<<<gabl, 256>>>(x1, agg2, n);
    gemm23<<<gblocks, 512, G2_SMEM>>>(agg2, x1,
                                      wh + 32768, wl + 32768,
                                      wh + 65536, wl + 65536,
                                      b2l, b3l, out_h1, out_h2, n);
}